// round 9
// baseline (speedup 1.0000x reference)
#include <cuda_runtime.h>
#include <cstddef>

// Problem constants
#define NN   50000
#define EE   800000
#define FF   512
#define HH   128
#define CC   40
#define TOTE (EE + NN)          // edges + self loops
#define SCAN_BS 512
#define SCAN_NB ((NN + SCAN_BS - 1) / SCAN_BS)   // 98

// ---- packed f32x2 helpers (Blackwell FFMA2) ---------------------------------
#define UNPK2(lo, hi, s) asm("mov.b64 {%0, %1}, %2;" : "=f"(lo), "=f"(hi) : "l"(s))
#define FMA2(d, a, b) asm("fma.rn.f32x2 %0, %1, %2, %0;" : "+l"(d) : "l"(a), "l"(b))

// ---------------- static scratch (device globals; no allocation) -------------
__device__ float g_deg[NN];
__device__ float g_dinv[NN];
__device__ int   g_cnt[NN];
__device__ int   g_rowptr[NN + 1];
__device__ int   g_bsum[SCAN_NB];
__device__ int   g_boff[SCAN_NB];
__device__ int   g_csrc[TOTE];
__device__ float g_cnorm[TOTE];

__device__ float g_cc[(size_t)NN * 640];   // [h | Sh | S2h | S3h | S4h]
__device__ float g_r[NN];
__device__ float g_sr[NN];
__device__ float g_s2r[NN];

__device__ float g_Acat[5 * HH * CC];      // 5 blocks of 128x40
__device__ float g_uc[CC];
__device__ float g_ur_p[3 * CC];           // contributions from branches 2,3,4
__device__ float g_usr_p[2 * CC];          // from branches 3,4
__device__ float g_us2r[CC];               // from branch 4

// ---------------- graph preprocessing ---------------------------------------

__global__ void k_init() {
    int i = blockIdx.x * blockDim.x + threadIdx.x;
    if (i < NN) { g_deg[i] = 1.0f; g_cnt[i] = 1; }   // self loop
}

__global__ void k_deg(const int* __restrict__ dst, const float* __restrict__ ew) {
    int e = blockIdx.x * blockDim.x + threadIdx.x;
    if (e < EE) {
        int d = dst[e];
        atomicAdd(&g_deg[d], ew[e]);
        atomicAdd(&g_cnt[d], 1);
    }
}

__global__ void k_scan1() {
    __shared__ int sh[SCAN_BS];
    int t = threadIdx.x;
    int idx = blockIdx.x * SCAN_BS + t;
    int v = (idx < NN) ? g_cnt[idx] : 0;
    sh[t] = v;
    __syncthreads();
    for (int off = 1; off < SCAN_BS; off <<= 1) {
        int x = (t >= off) ? sh[t - off] : 0;
        __syncthreads();
        sh[t] += x;
        __syncthreads();
    }
    if (idx < NN) g_rowptr[idx] = sh[t] - v;
    if (t == SCAN_BS - 1) g_bsum[blockIdx.x] = sh[t];
}

__global__ void k_scan2() {
    __shared__ int sh[128];
    int t = threadIdx.x;
    int v = (t < SCAN_NB) ? g_bsum[t] : 0;
    sh[t] = v;
    __syncthreads();
    for (int off = 1; off < 128; off <<= 1) {
        int x = (t >= off) ? sh[t - off] : 0;
        __syncthreads();
        sh[t] += x;
        __syncthreads();
    }
    if (t < SCAN_NB) g_boff[t] = sh[t] - v;   // exclusive
}

__global__ void k_scan3() {
    int t = threadIdx.x;
    int idx = blockIdx.x * SCAN_BS + t;
    if (idx < NN) g_rowptr[idx] += g_boff[blockIdx.x];
    if (idx == 0) g_rowptr[NN] = TOTE;
}

__global__ void k_dinv_self() {
    int n = blockIdx.x * blockDim.x + threadIdx.x;
    if (n < NN) {
        float di = rsqrtf(g_deg[n]);
        g_dinv[n] = di;
        int p = g_rowptr[n];
        g_csrc[p]  = n;
        g_cnorm[p] = di * di;
        g_cnt[n]   = 1;
    }
}

__global__ void k_fill(const int* __restrict__ src, const int* __restrict__ dst,
                       const float* __restrict__ ew) {
    int e = blockIdx.x * blockDim.x + threadIdx.x;
    if (e < EE) {
        int s = src[e], d = dst[e];
        int off = atomicAdd(&g_cnt[d], 1);
        int p = g_rowptr[d] + off;
        g_csrc[p]  = s;
        g_cnorm[p] = g_dinv[s] * ew[e] * g_dinv[d];
    }
}

// r-chain: vout[n] = sum_row cnorm * vin[src]   (vin==nullptr -> vin==1)
__global__ void __launch_bounds__(256) k_spmv_vec(const float* __restrict__ vin,
                                                  float* __restrict__ vout) {
    int w = (blockIdx.x * blockDim.x + threadIdx.x) >> 5;
    int lane = threadIdx.x & 31;
    if (w >= NN) return;
    int beg = g_rowptr[w], end = g_rowptr[w + 1];
    float a = 0.f;
    for (int i = beg + lane; i < end; i += 32)
        a += g_cnorm[i] * (vin ? vin[g_csrc[i]] : 1.0f);
    for (int o = 16; o; o >>= 1) a += __shfl_down_sync(0xffffffffu, a, o);
    if (lane == 0) vout[w] = a;
}

// ---------------- half-width dense GEMM --------------------------------------
// C[M, 64] = A[M,K] @ B[K, 64] + bias.  B has row stride 128 (caller offsets
// the column half).  Tile 128 rows x 64 cols, 256 threads.
// A tile stored DUPLICATED in smem so LDS.128 yields pre-packed (a,a) f32x2
// pairs; B float4s reinterpreted as ulonglong2 -> pack-free FFMA2 mainloop.
template<int K>
__global__ void __launch_bounds__(256) gemm_h64(
    const float* __restrict__ A, const float* __restrict__ B,
    const float* __restrict__ bias,
    float* __restrict__ C, int ldc, int M)
{
    __shared__ float  As[16][260];     // duplicated cols: [2r]=[2r+1]=a_r
    __shared__ float4 Bs4[16 * 16];    // 16 k x 16 float4 (64 cols)

    const int t = threadIdx.x;
    const int ty = t >> 4;        // 0..15 -> 8 rows
    const int tx = t & 15;        // 0..15 -> 4 cols (1 float4)
    const int ar  = t >> 2;       // 0..63
    const int seg = t & 3;        // 0..3
    const int rowbase = blockIdx.x * 128;

    unsigned long long acc[8][2];
#pragma unroll
    for (int i = 0; i < 8; i++) { acc[i][0] = 0ull; acc[i][1] = 0ull; }

    for (int kc = 0; kc < K; kc += 16) {
        // A tile: transpose + duplicate
#pragma unroll
        for (int rep = 0; rep < 2; rep++) {
            int r = ar + rep * 64;
            int row = rowbase + r;
            float4 av = make_float4(0.f, 0.f, 0.f, 0.f);
            if (row < M) av = *(const float4*)(A + (size_t)row * K + kc + seg * 4);
            *(float2*)&As[seg * 4 + 0][2 * r] = make_float2(av.x, av.x);
            *(float2*)&As[seg * 4 + 1][2 * r] = make_float2(av.y, av.y);
            *(float2*)&As[seg * 4 + 2][2 * r] = make_float2(av.z, av.z);
            *(float2*)&As[seg * 4 + 3][2 * r] = make_float2(av.w, av.w);
        }
        // B tile: one float4 per thread
        {
            int bk = t >> 4, bc = t & 15;
            Bs4[t] = *(const float4*)(B + (size_t)(kc + bk) * 128 + bc * 4);
        }
        __syncthreads();

#pragma unroll
        for (int k = 0; k < 16; k++) {
            ulonglong2 bp = *(const ulonglong2*)&Bs4[k * 16 + tx];
#pragma unroll
            for (int jj = 0; jj < 4; jj++) {
                ulonglong2 ap = *(const ulonglong2*)&As[k][ty * 16 + 4 * jj];
                FMA2(acc[2 * jj + 0][0], ap.x, bp.x);
                FMA2(acc[2 * jj + 0][1], ap.x, bp.y);
                FMA2(acc[2 * jj + 1][0], ap.y, bp.x);
                FMA2(acc[2 * jj + 1][1], ap.y, bp.y);
            }
        }
        __syncthreads();
    }

    float4 bb = ((const float4*)bias)[tx];
#pragma unroll
    for (int i = 0; i < 8; i++) {
        int row = rowbase + ty * 8 + i;
        if (row < M) {
            float4 r;
            UNPK2(r.x, r.y, acc[i][0]);
            UNPK2(r.z, r.w, acc[i][1]);
            r.x += bb.x; r.y += bb.y; r.z += bb.z; r.w += bb.w;
            ((float4*)(C + (size_t)row * ldc))[tx] = r;
        }
    }
}

// ---------------- half-width sparse aggregation ------------------------------
// Processes 64 of the 128 feature columns. in/out already offset to the half.
// One warp = 2 nodes, 16 lanes (4 float4s) per node.
__global__ void __launch_bounds__(256) agg_half(
    const float* __restrict__ in, float* __restrict__ out)
{
    int pair = (blockIdx.x * blockDim.x + threadIdx.x) >> 5;
    int lane = threadIdx.x & 31;
    int node = 2 * pair + (lane >> 4);
    int l    = lane & 15;
    if (node >= NN) return;

    int beg = g_rowptr[node];
    int end = g_rowptr[node + 1];
    const float4* in4 = (const float4*)in;

    float4 acc = make_float4(0.f, 0.f, 0.f, 0.f);
    int i = beg;
    for (; i + 1 < end; i += 2) {
        int s0 = g_csrc[i], s1 = g_csrc[i + 1];
        float w0 = g_cnorm[i], w1 = g_cnorm[i + 1];
        float4 v0 = in4[(size_t)s0 * 160 + l];
        float4 v1 = in4[(size_t)s1 * 160 + l];
        acc.x += w0 * v0.x + w1 * v1.x;
        acc.y += w0 * v0.y + w1 * v1.y;
        acc.z += w0 * v0.z + w1 * v1.z;
        acc.w += w0 * v0.w + w1 * v1.w;
    }
    if (i < end) {
        int s = g_csrc[i];
        float wt = g_cnorm[i];
        float4 v = in4[(size_t)s * 160 + l];
        acc.x += wt * v.x; acc.y += wt * v.y;
        acc.z += wt * v.z; acc.w += wt * v.w;
    }
    *(float4*)(out + (size_t)node * 640 + l * 4) = acc;
}

// ---------------- right-to-left weight chains --------------------------------
__global__ void __launch_bounds__(256) k_chains(
    const float* __restrict__ W_gcn, const float* __restrict__ b_gcn,
    const float* __restrict__ W_out, const float* __restrict__ b_out)
{
    __shared__ float tA[HH * CC];
    __shared__ float tB[HH * CC];
    const int b = blockIdx.x;
    const int t = threadIdx.x;

    if (b == 0) {
        for (int i = t; i < HH * CC; i += 256) g_Acat[i] = W_out[i];
        if (t < CC) {
            float s = b_out[t];
            for (int k = 0; k < HH; k++) {
                s += b_gcn[0 * HH + k] * W_out[(size_t)(1 * HH + k) * CC + t];
                s += b_gcn[2 * HH + k] * W_out[(size_t)(2 * HH + k) * CC + t];
                s += b_gcn[5 * HH + k] * W_out[(size_t)(3 * HH + k) * CC + t];
                s += b_gcn[9 * HH + k] * W_out[(size_t)(4 * HH + k) * CC + t];
            }
            g_uc[t] = s;
        }
        return;
    }

    for (int i = t; i < HH * CC; i += 256) tA[i] = W_out[(size_t)b * HH * CC + i];
    __syncthreads();

    float* cur = tA;
    float* nxt = tB;
    const int start = (b - 1) * b / 2;

    const int row = t >> 1;     // 0..127
    const int half = t & 1;     // 0..1 -> 20 cols each

    for (int p = 1; p <= b; p++) {
        const float* Wr = W_gcn + (size_t)(start + b - p) * HH * HH + (size_t)row * HH;
        float acc[20];
#pragma unroll
        for (int c = 0; c < 20; c++) acc[c] = 0.f;
        for (int k = 0; k < HH; k++) {
            float a = Wr[k];
            const float* srcp = cur + k * CC + half * 20;
#pragma unroll
            for (int c = 0; c < 20; c++) acc[c] += a * srcp[c];
        }
        float* dstp = nxt + row * CC + half * 20;
#pragma unroll
        for (int c = 0; c < 20; c++) dstp[c] = acc[c];
        __syncthreads();

        if (p < b && t < CC) {
            const float* bb = b_gcn + (size_t)(start + b - p - 1) * HH;
            float s = 0.f;
            for (int k = 0; k < HH; k++) s += bb[k] * nxt[k * CC + t];
            if (p == 1)      g_ur_p[(b - 2) * CC + t] = s;
            else if (p == 2) g_usr_p[(b - 3) * CC + t] = s;
            else             g_us2r[t] = s;
        }
        float* tmp = cur; cur = nxt; nxt = tmp;
    }

    for (int i = t; i < HH * CC; i += 256)
        g_Acat[(size_t)b * HH * CC + i] = cur[i];
}

// ---------------- partial output GEMM: C (+)= q[M,128] @ Aj[128,40] ----------
template<bool INIT>
__global__ void __launch_bounds__(256) k_pout(
    const float* __restrict__ q, const float* __restrict__ Aj,
    float* __restrict__ C, int M)
{
    __shared__ float Bsf[HH * CC];
    __shared__ float As[16][129];
    __shared__ float su_c[CC], su_r[CC], su_sr[CC], su_s2r[CC];

    const int t = threadIdx.x;
    for (int i = t; i < HH * CC; i += 256) Bsf[i] = Aj[i];
    if (INIT && t < CC) {
        su_c[t]   = g_uc[t];
        su_r[t]   = g_ur_p[t] + g_ur_p[CC + t] + g_ur_p[2 * CC + t];
        su_sr[t]  = g_usr_p[t] + g_usr_p[CC + t];
        su_s2r[t] = g_us2r[t];
    }

    const int rg = t >> 3;   // 0..31
    const int cg = t & 7;    // 0..7
    const int rowbase = blockIdx.x * 128;

    float acc[4][5];
#pragma unroll
    for (int i = 0; i < 4; i++)
#pragma unroll
        for (int j = 0; j < 5; j++) acc[i][j] = 0.f;

    for (int kc = 0; kc < HH; kc += 16) {
#pragma unroll
        for (int rep = 0; rep < 2; rep++) {
            int idx = t + rep * 256;
            int r = idx >> 2, seg = idx & 3;
            int row = rowbase + r;
            float4 av = make_float4(0.f, 0.f, 0.f, 0.f);
            if (row < M) av = *(const float4*)(q + (size_t)row * 640 + kc + seg * 4);
            As[seg * 4 + 0][r] = av.x;
            As[seg * 4 + 1][r] = av.y;
            As[seg * 4 + 2][r] = av.z;
            As[seg * 4 + 3][r] = av.w;
        }
        __syncthreads();

#pragma unroll
        for (int k = 0; k < 16; k++) {
            float a0 = As[k][rg], a1 = As[k][rg + 32], a2 = As[k][rg + 64], a3 = As[k][rg + 96];
#pragma unroll
            for (int j = 0; j < 5; j++) {
                float bv = Bsf[(kc + k) * CC + cg + 8 * j];
                acc[0][j] += a0 * bv; acc[1][j] += a1 * bv;
                acc[2][j] += a2 * bv; acc[3][j] += a3 * bv;
            }
        }
        __syncthreads();
    }

#pragma unroll
    for (int i = 0; i < 4; i++) {
        int row = rowbase + rg + 32 * i;
        if (row < M) {
            if (INIT) {
                float rv = g_r[row], srv = g_sr[row], s2rv = g_s2r[row];
#pragma unroll
                for (int j = 0; j < 5; j++) {
                    int col = cg + 8 * j;
                    C[(size_t)row * CC + col] = acc[i][j] + su_c[col]
                        + rv * su_r[col] + srv * su_sr[col] + s2rv * su_s2r[col];
                }
            } else {
#pragma unroll
                for (int j = 0; j < 5; j++) {
                    int col = cg + 8 * j;
                    C[(size_t)row * CC + col] += acc[i][j];
                }
            }
        }
    }
}

// ---------------- stream/event setup at static-init (outside checkpoints) ----
struct StreamInit {
    bool ok = false;
    int dev = -1;
    cudaStream_t sB{}, sC{};
    cudaEvent_t ev[16]{};
    StreamInit() {
        ok = (cudaStreamCreateWithFlags(&sB, cudaStreamNonBlocking) == cudaSuccess) &&
             (cudaStreamCreateWithFlags(&sC, cudaStreamNonBlocking) == cudaSuccess);
        for (int i = 0; i < 16 && ok; i++)
            ok = (cudaEventCreateWithFlags(&ev[i], cudaEventDisableTiming) == cudaSuccess);
        if (ok) cudaGetDevice(&dev);
    }
};
static StreamInit g_si;

// ---------------- host driver ------------------------------------------------

extern "C" void kernel_launch(void* const* d_in, const int* in_sizes, int n_in,
                              void* d_out, int out_size)
{
    (void)in_sizes; (void)n_in; (void)out_size;

    const float* x     = (const float*)d_in[0];
    const int*   ei    = (const int*)d_in[1];
    const float* ew    = (const float*)d_in[2];
    const float* W_in  = (const float*)d_in[3];
    const float* b_in  = (const float*)d_in[4];
    const float* W_gcn = (const float*)d_in[5];  // [10,128,128]
    const float* b_gcn = (const float*)d_in[6];  // [10,128]
    const float* W_out = (const float*)d_in[7];  // [640,40]
    const float* b_out = (const float*)d_in[8];
    float* outp = (float*)d_out;

    const int* src = ei;
    const int* dst = ei + EE;

    float *p_cc, *p_r, *p_sr, *p_s2r, *p_acat;
    cudaGetSymbolAddress((void**)&p_cc,   g_cc);
    cudaGetSymbolAddress((void**)&p_r,    g_r);
    cudaGetSymbolAddress((void**)&p_sr,   g_sr);
    cudaGetSymbolAddress((void**)&p_s2r,  g_s2r);
    cudaGetSymbolAddress((void**)&p_acat, g_Acat);

    int curdev = -1;
    cudaGetDevice(&curdev);
    const bool par = g_si.ok && (curdev == g_si.dev);
    cudaStream_t s0 = 0;
    cudaStream_t sB = par ? g_si.sB : (cudaStream_t)0;
    cudaStream_t sC = par ? g_si.sC : (cudaStream_t)0;
    cudaEvent_t e0   = g_si.ev[0];
    cudaEvent_t eG0  = g_si.ev[1], eG1 = g_si.ev[2];
    cudaEvent_t eW   = g_si.ev[3], eCSR = g_si.ev[4], eR = g_si.ev[5];
    cudaEvent_t* ec0 = &g_si.ev[6];    // 6..9
    cudaEvent_t* ec1 = &g_si.ev[10];   // 10..13
    cudaEvent_t eF   = g_si.ev[14];

    // fork
    if (par) {
        cudaEventRecord(e0, s0);
        cudaStreamWaitEvent(sB, e0, 0);
        cudaStreamWaitEvent(sC, e0, 0);
    }

    const int GT = (NN + 127) / 128;     // 391 row tiles

    // sB: input linear in two column halves -> cc block 0
    gemm_h64<FF><<<GT, 256, 0, sB>>>(x, W_in,      b_in,      p_cc,      640, NN);
    if (par) cudaEventRecord(eG0, sB);
    gemm_h64<FF><<<GT, 256, 0, sB>>>(x, W_in + 64, b_in + 64, p_cc + 64, 640, NN);
    if (par) cudaEventRecord(eG1, sB);

    // sC: weight chains (Acat + bias folds)
    k_chains<<<5, 256, 0, sC>>>(W_gcn, b_gcn, W_out, b_out);
    if (par) cudaEventRecord(eW, sC);

    // s0: CSR build
    k_init<<<(NN + 255) / 256, 256, 0, s0>>>();
    k_deg<<<(EE + 255) / 256, 256, 0, s0>>>(dst, ew);
    k_scan1<<<SCAN_NB, SCAN_BS, 0, s0>>>();
    k_scan2<<<1, 128, 0, s0>>>();
    k_scan3<<<SCAN_NB, SCAN_BS, 0, s0>>>();
    k_dinv_self<<<(NN + 255) / 256, 256, 0, s0>>>();
    k_fill<<<(EE + 255) / 256, 256, 0, s0>>>(src, dst, ew);
    if (par) cudaEventRecord(eCSR, s0);

    // sC: r chain (after CSR)
    const int VEC_GRID = (NN * 32 + 255) / 256;
    if (par) cudaStreamWaitEvent(sC, eCSR, 0);
    k_spmv_vec<<<VEC_GRID, 256, 0, sC>>>(nullptr, p_r);
    k_spmv_vec<<<VEC_GRID, 256, 0, sC>>>(p_r, p_sr);
    k_spmv_vec<<<VEC_GRID, 256, 0, sC>>>(p_sr, p_s2r);
    if (par) cudaEventRecord(eR, sC);

    // s0: aggregation chain, half 0 (CSR already ordered on s0; needs h half0)
    const int AGG_GRID = (NN / 2 * 32 + 255) / 256;   // 2 nodes per warp
    if (par) cudaStreamWaitEvent(s0, eG0, 0);
    for (int j = 0; j < 4; j++) {
        agg_half<<<AGG_GRID, 256, 0, s0>>>(p_cc + j * HH, p_cc + (j + 1) * HH);
        if (par) cudaEventRecord(ec0[j], s0);
    }

    // sC: aggregation chain, half 1 (needs CSR [ordered on sC via eCSR] + h half1)
    if (par) cudaStreamWaitEvent(sC, eG1, 0);
    for (int j = 0; j < 4; j++) {
        agg_half<<<AGG_GRID, 256, 0, sC>>>(p_cc + j * HH + 64, p_cc + (j + 1) * HH + 64);
        if (par) cudaEventRecord(ec1[j], sC);
    }

    // sB: partial output GEMMs as each q block completes (both halves)
    const int PG = (NN + 127) / 128;
    if (par) { cudaStreamWaitEvent(sB, eW, 0); cudaStreamWaitEvent(sB, eR, 0); }
    k_pout<true><<<PG, 256, 0, sB>>>(p_cc + 0 * HH, p_acat + 0 * HH * CC, outp, NN);
    for (int j = 0; j < 4; j++) {
        if (par) { cudaStreamWaitEvent(sB, ec0[j], 0); cudaStreamWaitEvent(sB, ec1[j], 0); }
        k_pout<false><<<PG, 256, 0, sB>>>(p_cc + (j + 1) * HH, p_acat + (j + 1) * HH * CC, outp, NN);
    }

    // join back to capture stream
    if (par) {
        cudaEventRecord(eF, sB);
        cudaStreamWaitEvent(s0, eF, 0);
    }
}